// round 3
// baseline (speedup 1.0000x reference)
#include <cuda_runtime.h>
#include <cuda_bf16.h>
#include <math.h>

#define BSZ 4
#define NV  4096
#define NP1 1024
#define NP2 256
#define KNN 32

typedef unsigned long long u64;

// ---------------- scratch (device globals; no allocation allowed) ------------
__device__ int   g_nb1[BSZ*NV*KNN];
__device__ int   g_nb2[BSZ*NP1*KNN];
__device__ int   g_nb3[BSZ*NP2*KNN];
__device__ int   g_nbp[BSZ*NP1*4];
__device__ int   g_near1[BSZ*NV];
__device__ int   g_near2[BSZ*NV];
__device__ float g_fm0[BSZ*NV*128];
__device__ float g_fm1[BSZ*NV*128];
__device__ float g_f  [BSZ*NV*256];
__device__ float g_vp1[BSZ*NP1*3];
__device__ float g_fmp1[BSZ*NP1*128];
__device__ float g_fm2[BSZ*NP1*256];
__device__ float g_fm3[BSZ*NP1*256];
__device__ float g_vp2[BSZ*NP2*3];
__device__ float g_fmp2[BSZ*NP2*256];
__device__ float g_fm4[BSZ*NP2*512];
__device__ float g_fglob[BSZ*512];
__device__ float g_fuse[BSZ*NV*1792];
__device__ float g_h1[BSZ*NV*512];
__device__ float g_h2[BSZ*NV*512];

// ---------------- packed f32x2 helpers (SASS FFMA2) --------------------------
__device__ __forceinline__ u64 pk2(float x) {
    u64 r;
    asm("mov.b64 %0, {%1, %1};" : "=l"(r) : "f"(x));
    return r;
}
__device__ __forceinline__ void ffma2(u64& d, u64 a, u64 b) {
    asm("fma.rn.f32x2 %0, %1, %2, %0;" : "+l"(d) : "l"(a), "l"(b));
}
__device__ __forceinline__ float2 upk(u64 p) {
    float2 f;
    asm("mov.b64 {%0, %1}, %2;" : "=f"(f.x), "=f"(f.y) : "l"(p));
    return f;
}

// ---------------- KNN: brute force, smem-tiled, insertion top-K --------------
template<int K>
__global__ void knn_kernel(const float* __restrict__ verts,
                           const int* __restrict__ qidx, // null => identity
                           int nq, int V, int* __restrict__ out)
{
    int b = blockIdx.y;
    int q = blockIdx.x * 128 + threadIdx.x;
    const float* vb = verts + (size_t)b * V * 3;
    bool active = q < nq;
    int self = -1;
    float qx=0.f, qy=0.f, qz=0.f, qa2=0.f;
    if (active) {
        self = qidx ? qidx[q] : q;
        qx = vb[self*3+0]; qy = vb[self*3+1]; qz = vb[self*3+2];
        qa2 = qx*qx + qy*qy + qz*qz;
    }
    float dk[K]; int ik[K];
#pragma unroll
    for (int i=0;i<K;i++){ dk[i]=3.4e38f; ik[i]=0; }
    float worst = 3.4e38f;

    __shared__ float4 sp[128];
    for (int t0=0; t0<V; t0+=128) {
        int j = t0 + threadIdx.x;   // V is a multiple of 128 always
        float x = vb[j*3+0], y = vb[j*3+1], z = vb[j*3+2];
        sp[threadIdx.x] = make_float4(x,y,z, x*x+y*y+z*z);
        __syncthreads();
        if (active) {
            for (int jj=0; jj<128; jj++) {
                float4 p = sp[jj];
                float d = qa2 + p.w - 2.0f*(qx*p.x + qy*p.y + qz*p.z);
                int gj = t0 + jj;
                if (gj != self && d < worst) {
                    int pos = K-1;
                    while (pos > 0 && dk[pos-1] > d) {
                        dk[pos]=dk[pos-1]; ik[pos]=ik[pos-1]; --pos;
                    }
                    dk[pos]=d; ik[pos]=gj;
                    worst = dk[K-1];
                }
            }
        }
        __syncthreads();
    }
    if (active) {
        int* o = out + ((size_t)b*nq + q)*K;
#pragma unroll
        for (int i=0;i<K;i++) o[i]=ik[i];
    }
}

// ---------------- conv_surface (fm0) ----------------------------------------
__global__ void conv_surface_kernel(const float* __restrict__ verts,
                                    const int* __restrict__ nb,
                                    const float* __restrict__ dir0,
                                    float* __restrict__ fm0)
{
    int bv = blockIdx.x;               // b*NV + v
    int b = bv >> 12, v = bv & (NV-1);
    const float* vb = verts + (size_t)b*NV*3;
    __shared__ float sdx[KNN], sdy[KNN], sdz[KNN];
    int t = threadIdx.x;
    float cx = vb[v*3+0], cy = vb[v*3+1], cz = vb[v*3+2];
    if (t < KNN) {
        int j = nb[(size_t)bv*KNN + t];
        float dx = vb[j*3+0]-cx, dy = vb[j*3+1]-cy, dz = vb[j*3+2]-cz;
        float n = sqrtf(dx*dx+dy*dy+dz*dz);
        float inv = 1.0f / fmaxf(n, 1e-12f);
        sdx[t]=dx*inv; sdy[t]=dy*inv; sdz[t]=dz*inv;
    }
    __syncthreads();
    int k = t;                          // 128 threads = 128 kernels
    float d0 = dir0[k], d1 = dir0[128+k], d2 = dir0[256+k];
    float n = sqrtf(d0*d0+d1*d1+d2*d2);
    float inv = 1.0f / fmaxf(n, 1e-12f);
    d0*=inv; d1*=inv; d2*=inv;
    float m = 0.0f;
#pragma unroll
    for (int j=0;j<KNN;j++)
        m = fmaxf(m, sdx[j]*d0 + sdy[j]*d1 + sdz[j]*d2);
    fm0[(size_t)bv*128 + k] = m;
}

// ---------------- conv_layer epilogue: center + max_n(theta * supp_nb) ------
template<int COUT, bool RELU>
__global__ void conv_layer_kernel(const float* __restrict__ verts, int V,
                                  const int* __restrict__ nb,
                                  const float* __restrict__ f,    // (B*V, 2*COUT)
                                  const float* __restrict__ dirs, // (3, COUT)
                                  float* __restrict__ out)        // (B*V, COUT)
{
    int bv = blockIdx.x;
    int b = bv / V, v = bv - b*V;
    const float* vb = verts + (size_t)b*V*3;
    __shared__ float sdx[KNN], sdy[KNN], sdz[KNN];
    __shared__ int   si[KNN];
    int t = threadIdx.x;
    float cx = vb[v*3+0], cy = vb[v*3+1], cz = vb[v*3+2];
    if (t < KNN) {
        int j = nb[(size_t)bv*KNN + t];
        si[t] = j;
        float dx = vb[j*3+0]-cx, dy = vb[j*3+1]-cy, dz = vb[j*3+2]-cz;
        float n = sqrtf(dx*dx+dy*dy+dz*dz);
        float inv = 1.0f / fmaxf(n, 1e-12f);
        sdx[t]=dx*inv; sdy[t]=dy*inv; sdz[t]=dz*inv;
    }
    __syncthreads();
    const float* fb = f + (size_t)b*V*(2*COUT);
    for (int co = t; co < COUT; co += blockDim.x) {
        float d0 = dirs[co], d1 = dirs[COUT+co], d2 = dirs[2*COUT+co];
        float n = sqrtf(d0*d0+d1*d1+d2*d2);
        float inv = 1.0f / fmaxf(n, 1e-12f);
        d0*=inv; d1*=inv; d2*=inv;
        float m = -3.4e38f;
#pragma unroll 8
        for (int j=0;j<KNN;j++) {
            float th = fmaxf(sdx[j]*d0 + sdy[j]*d1 + sdz[j]*d2, 0.0f);
            float val = th * fb[(size_t)si[j]*(2*COUT) + COUT + co];
            m = fmaxf(m, val);
        }
        float r = fb[(size_t)v*(2*COUT) + co] + m;
        out[((size_t)b*V+v)*COUT + co] = RELU ? fmaxf(r, 0.0f) : r;
    }
}

// ---------------- pool: gather sampled verts + max over 4 NN ----------------
__global__ void pool_kernel(const float* __restrict__ verts,
                            const float* __restrict__ fm,
                            int V, int C,
                            const int* __restrict__ sidx,
                            const int* __restrict__ nb4, int ns,
                            float* __restrict__ vout, float* __restrict__ fout)
{
    int bq = blockIdx.x;
    int b = bq / ns, q = bq - b*ns;
    int t = threadIdx.x;
    int sv = sidx[q];
    if (t < 3) vout[(size_t)bq*3 + t] = verts[((size_t)b*V + sv)*3 + t];
    const int* nbq = nb4 + (size_t)bq*4;
    int j0=nbq[0], j1=nbq[1], j2=nbq[2], j3=nbq[3];
    const float* fb = fm + (size_t)b*V*C;
    for (int c=t; c<C; c+=blockDim.x) {
        float m = fmaxf(fmaxf(fb[(size_t)j0*C+c], fb[(size_t)j1*C+c]),
                        fmaxf(fb[(size_t)j2*C+c], fb[(size_t)j3*C+c]));
        fout[(size_t)bq*C + c] = m;
    }
}

// ---------------- nearest: argmin over source set (first-min wins) ----------
__global__ void nearest_kernel(const float* __restrict__ verts,
                               const float* __restrict__ src,
                               int V, int S, int* __restrict__ out)
{
    int b = blockIdx.y;
    int q = blockIdx.x * 128 + threadIdx.x;
    const float* vb = verts + (size_t)b*V*3;
    const float* sb = src + (size_t)b*S*3;
    float qx = vb[q*3+0], qy = vb[q*3+1], qz = vb[q*3+2];
    float qa2 = qx*qx + qy*qy + qz*qz;
    float best = 3.4e38f; int bi = 0;
    __shared__ float4 sp[128];
    for (int t0=0; t0<S; t0+=128) {
        int j = t0 + threadIdx.x;
        float x = sb[j*3+0], y = sb[j*3+1], z = sb[j*3+2];
        sp[threadIdx.x] = make_float4(x,y,z, x*x+y*y+z*z);
        __syncthreads();
        for (int jj=0; jj<128; jj++) {
            float4 p = sp[jj];
            float d = qa2 + p.w - 2.0f*(qx*p.x + qy*p.y + qz*p.z);
            if (d < best) { best = d; bi = t0+jj; }
        }
        __syncthreads();
    }
    out[(size_t)b*V + q] = bi;
}

// ---------------- global feature: max over NP2 verts ------------------------
__global__ void fglobal_kernel(const float* __restrict__ fm4, float* __restrict__ g)
{
    int b = blockIdx.x, c = threadIdx.x;   // 512 threads
    float m = -3.4e38f;
    for (int v=0; v<NP2; v++) m = fmaxf(m, fm4[((size_t)b*NP2+v)*512 + c]);
    g[(size_t)b*512 + c] = m;
}

// ---------------- fuse assembly ----------------------------------------------
__global__ void fuse_kernel(const float* __restrict__ fm0, const float* __restrict__ fm1,
                            const float* __restrict__ fm2, const float* __restrict__ fm3,
                            const float* __restrict__ fm4, const float* __restrict__ fg,
                            const int* __restrict__ near1, const int* __restrict__ near2,
                            float* __restrict__ fuse)
{
    int bv = blockIdx.x;
    int b = bv >> 12;
    int n1 = near1[bv], n2 = near2[bv];
    float* o = fuse + (size_t)bv*1792;
    for (int c = threadIdx.x; c < 1792; c += blockDim.x) {
        float val;
        if (c < 128)        val = fm0[(size_t)bv*128 + c];
        else if (c < 256)   val = fm1[(size_t)bv*128 + (c-128)];
        else if (c < 512)   val = fm2[((size_t)b*NP1+n1)*256 + (c-256)];
        else if (c < 768)   val = fm3[((size_t)b*NP1+n1)*256 + (c-512)];
        else if (c < 1280)  val = fm4[((size_t)b*NP2+n2)*512 + (c-768)];
        else                val = fg [(size_t)b*512 + (c-1280)];
        o[c] = val;
    }
}

// ---------------- SGEMM 128x128x8, 8x8 micro-tile, f32x2 FFMA2 --------------
// REQUIREMENTS (guaranteed by call sites): M%128==0, N%128==0, K%8==0,
// A/B/C 16B-aligned.  BT=false: B is (K,N) row-major.  BT=true: B is (N,K).
#define SMS 132   // smem row stride (floats): 16B-aligned (528B)
template<bool BT, bool RELU>
__global__ __launch_bounds__(256, 2)
void gemm128(const float* __restrict__ A, const float* __restrict__ B,
             const float* __restrict__ bias, float* __restrict__ C,
             int M, int N, int K)
{
    __shared__ __align__(16) float As[2][8*SMS];
    __shared__ __align__(16) float Bs[2][8*SMS];
    const int tid = threadIdx.x;
    const int tx = tid & 15;        // n-direction
    const int ty = tid >> 4;        // m-direction
    const int m0 = blockIdx.y * 128;
    const int n0 = blockIdx.x * 128;

    // A global load: thread -> (row = tid>>1, kpart = (tid&1)*4), one float4
    const int arow = tid >> 1;
    const int akp  = (tid & 1) * 4;
    const float* Aptr = A + (size_t)(m0 + arow) * K + akp;

    // B global load
    const float* Bptr;
    int bkk = 0, bn4 = 0;
    if (BT) {
        Bptr = B + (size_t)(n0 + arow) * K + akp;   // same decomposition as A
    } else {
        bkk = tid >> 5; bn4 = (tid & 31) * 4;
        Bptr = B + (size_t)bkk * N + n0 + bn4;
    }

    u64 acc2[8][4];                 // [m][n-pair]; each u64 = 2 packed fp32 cols
#pragma unroll
    for (int i=0;i<8;i++)
#pragma unroll
        for (int j=0;j<4;j++) acc2[i][j]=0ULL;

    const int NT = K >> 3;

    // prologue: tile 0
    float4 areg = *(const float4*)Aptr;
    float4 breg = *(const float4*)Bptr;
    As[0][(akp+0)*SMS+arow]=areg.x;
    As[0][(akp+1)*SMS+arow]=areg.y;
    As[0][(akp+2)*SMS+arow]=areg.z;
    As[0][(akp+3)*SMS+arow]=areg.w;
    if (BT) {
        Bs[0][(akp+0)*SMS+arow]=breg.x;
        Bs[0][(akp+1)*SMS+arow]=breg.y;
        Bs[0][(akp+2)*SMS+arow]=breg.z;
        Bs[0][(akp+3)*SMS+arow]=breg.w;
    } else {
        *(float4*)&Bs[0][bkk*SMS+bn4] = breg;
    }
    __syncthreads();

    for (int kt=0; kt<NT; kt++) {
        const int cur = kt & 1;
        if (kt+1 < NT) {
            areg = *(const float4*)(Aptr + (size_t)(kt+1)*8);
            if (BT) breg = *(const float4*)(Bptr + (size_t)(kt+1)*8);
            else    breg = *(const float4*)(Bptr + (size_t)(kt+1)*8*N);
        }
        const float* as = As[cur];
        const float* bs = Bs[cur];
#pragma unroll
        for (int kk=0; kk<8; kk++) {
            float4 a0 = *(const float4*)&as[kk*SMS + ty*4];
            float4 a1 = *(const float4*)&as[kk*SMS + 64 + ty*4];
            ulonglong2 b0 = *(const ulonglong2*)&bs[kk*SMS + tx*4];
            ulonglong2 b1 = *(const ulonglong2*)&bs[kk*SMS + 64 + tx*4];
            u64 bp[4] = {b0.x, b0.y, b1.x, b1.y};
            u64 ap[8] = {pk2(a0.x), pk2(a0.y), pk2(a0.z), pk2(a0.w),
                         pk2(a1.x), pk2(a1.y), pk2(a1.z), pk2(a1.w)};
#pragma unroll
            for (int i=0;i<8;i++)
#pragma unroll
                for (int j=0;j<4;j++)
                    ffma2(acc2[i][j], ap[i], bp[j]);
        }
        if (kt+1 < NT) {
            const int nxt = cur ^ 1;
            As[nxt][(akp+0)*SMS+arow]=areg.x;
            As[nxt][(akp+1)*SMS+arow]=areg.y;
            As[nxt][(akp+2)*SMS+arow]=areg.z;
            As[nxt][(akp+3)*SMS+arow]=areg.w;
            if (BT) {
                Bs[nxt][(akp+0)*SMS+arow]=breg.x;
                Bs[nxt][(akp+1)*SMS+arow]=breg.y;
                Bs[nxt][(akp+2)*SMS+arow]=breg.z;
                Bs[nxt][(akp+3)*SMS+arow]=breg.w;
            } else {
                *(float4*)&Bs[nxt][bkk*SMS+bn4] = breg;
            }
        }
        __syncthreads();
    }

    // epilogue: bias (+relu), float4 stores
#pragma unroll
    for (int ih=0; ih<2; ih++)
#pragma unroll
    for (int ii=0; ii<4; ii++) {
        const int i = ih*4 + ii;
        const int gm = m0 + ih*64 + ty*4 + ii;
        float* crow = C + (size_t)gm*N + n0;
#pragma unroll
        for (int jh=0; jh<2; jh++) {
            const int cb = jh*64 + tx*4;
            float4 bv = *(const float4*)&bias[n0 + cb];
            float2 v0 = upk(acc2[i][jh*2+0]);
            float2 v1 = upk(acc2[i][jh*2+1]);
            float4 v;
            v.x = v0.x + bv.x;
            v.y = v0.y + bv.y;
            v.z = v1.x + bv.z;
            v.w = v1.y + bv.w;
            if (RELU) {
                v.x = fmaxf(v.x, 0.f); v.y = fmaxf(v.y, 0.f);
                v.z = fmaxf(v.z, 0.f); v.w = fmaxf(v.w, 0.f);
            }
            *(float4*)&crow[cb] = v;
        }
    }
}

// ---------------- head: out(16 rows x 13) = h2 @ cw3^T + cb3 ----------------
__global__ void head_kernel(const float* __restrict__ h2,
                            const float* __restrict__ cw3,
                            const float* __restrict__ cb3,
                            float* __restrict__ out)
{
    __shared__ float sh[16][512];
    __shared__ float sw[13*513];
    const int tid = threadIdx.x;            // 256 threads
    const int r = tid >> 4, c = tid & 15;
    const int row0 = blockIdx.x * 16;
    for (int i = tid; i < 16*512; i += 256)
        sh[i>>9][i&511] = h2[(size_t)row0*512 + i];
    for (int i = tid; i < 13*512; i += 256)
        sw[(i>>9)*513 + (i&511)] = cw3[i];
    __syncthreads();
    if (c < 13) {
        float acc = cb3[c];
        const float* w = &sw[c*513];
        const float* hrow = sh[r];
#pragma unroll 8
        for (int k=0;k<512;k++) acc += hrow[k]*w[k];
        out[(size_t)(row0+r)*13 + c] = acc;
    }
}

// -----------------------------------------------------------------------------
static void* sym_addr(const void* symbol) {
    void* p = nullptr;
    cudaGetSymbolAddress(&p, symbol);
    return p;
}

extern "C" void kernel_launch(void* const* d_in, const int* in_sizes, int n_in,
                              void* d_out, int out_size)
{
    (void)in_sizes; (void)n_in; (void)out_size;
    const float* vertices = (const float*)d_in[0];
    const int*   sidx1    = (const int*)  d_in[1];
    const int*   sidx2    = (const int*)  d_in[2];
    const float* dir0     = (const float*)d_in[3];
    const float* w1 = (const float*)d_in[4];  const float* b1 = (const float*)d_in[5];  const float* d1 = (const float*)d_in[6];
    const float* w2 = (const float*)d_in[7];  const float* b2 = (const float*)d_in[8];  const float* d2 = (const float*)d_in[9];
    const float* w3 = (const float*)d_in[10]; const float* b3 = (const float*)d_in[11]; const float* d3 = (const float*)d_in[12];
    const float* w4 = (const float*)d_in[13]; const float* b4 = (const float*)d_in[14]; const float* d4 = (const float*)d_in[15];
    const float* cw1 = (const float*)d_in[16]; const float* cb1 = (const float*)d_in[17];
    const float* cw2 = (const float*)d_in[18]; const float* cb2 = (const float*)d_in[19];
    const float* cw3 = (const float*)d_in[20]; const float* cb3 = (const float*)d_in[21];
    float* out = (float*)d_out;

    int*   nb1   = (int*)  sym_addr(g_nb1);
    int*   nb2   = (int*)  sym_addr(g_nb2);
    int*   nb3   = (int*)  sym_addr(g_nb3);
    int*   nbp   = (int*)  sym_addr(g_nbp);
    int*   near1 = (int*)  sym_addr(g_near1);
    int*   near2 = (int*)  sym_addr(g_near2);
    float* fm0   = (float*)sym_addr(g_fm0);
    float* fm1   = (float*)sym_addr(g_fm1);
    float* fbuf  = (float*)sym_addr(g_f);
    float* vp1   = (float*)sym_addr(g_vp1);
    float* fmp1  = (float*)sym_addr(g_fmp1);
    float* fm2   = (float*)sym_addr(g_fm2);
    float* fm3   = (float*)sym_addr(g_fm3);
    float* vp2   = (float*)sym_addr(g_vp2);
    float* fmp2  = (float*)sym_addr(g_fmp2);
    float* fm4   = (float*)sym_addr(g_fm4);
    float* fglob = (float*)sym_addr(g_fglob);
    float* fuse  = (float*)sym_addr(g_fuse);
    float* h1    = (float*)sym_addr(g_h1);
    float* h2    = (float*)sym_addr(g_h2);

    // 1. full-res KNN(32)
    knn_kernel<KNN><<<dim3(NV/128, BSZ), 128>>>(vertices, nullptr, NV, NV, nb1);
    // 2. fm0 = conv_surface
    conv_surface_kernel<<<BSZ*NV, 128>>>(vertices, nb1, dir0, fm0);
    // 3-4. fm1 = relu(conv_layer(fm0; w1,b1,d1; 128))
    gemm128<false,false><<<dim3(256/128, (BSZ*NV)/128), 256>>>(fm0, w1, b1, fbuf, BSZ*NV, 256, 128);
    conv_layer_kernel<128,true><<<BSZ*NV, 128>>>(vertices, NV, nb1, fbuf, d1, fm1);
    // 5-6. pool1
    knn_kernel<4><<<dim3(NP1/128, BSZ), 128>>>(vertices, sidx1, NP1, NV, nbp);
    pool_kernel<<<BSZ*NP1, 128>>>(vertices, fm1, NV, 128, sidx1, nbp, NP1, vp1, fmp1);
    // 7. KNN(32) on pooled level 1
    knn_kernel<KNN><<<dim3(NP1/128, BSZ), 128>>>(vp1, nullptr, NP1, NP1, nb2);
    // 8-9. fm2 = relu(conv_layer(fmp1; w2,b2,d2; 256))
    gemm128<false,false><<<dim3(512/128, (BSZ*NP1)/128), 256>>>(fmp1, w2, b2, fbuf, BSZ*NP1, 512, 128);
    conv_layer_kernel<256,true><<<BSZ*NP1, 256>>>(vp1, NP1, nb2, fbuf, d2, fm2);
    // 10-11. fm3 = relu(conv_layer(fm2; w3,b3,d3; 256))
    gemm128<false,false><<<dim3(512/128, (BSZ*NP1)/128), 256>>>(fm2, w3, b3, fbuf, BSZ*NP1, 512, 256);
    conv_layer_kernel<256,true><<<BSZ*NP1, 256>>>(vp1, NP1, nb2, fbuf, d3, fm3);
    // 12-13. pool2
    knn_kernel<4><<<dim3(NP2/128, BSZ), 128>>>(vp1, sidx2, NP2, NP1, nbp);
    pool_kernel<<<BSZ*NP2, 256>>>(vp1, fm3, NP1, 256, sidx2, nbp, NP2, vp2, fmp2);
    // 14. KNN(32) on pooled level 2
    knn_kernel<KNN><<<dim3(NP2/128, BSZ), 128>>>(vp2, nullptr, NP2, NP2, nb3);
    // 15-16. fm4 = conv_layer(fmp2; w4,b4,d4; 512)  (no relu)
    gemm128<false,false><<<dim3(1024/128, (BSZ*NP2)/128), 256>>>(fmp2, w4, b4, fbuf, BSZ*NP2, 1024, 256);
    conv_layer_kernel<512,false><<<BSZ*NP2, 256>>>(vp2, NP2, nb3, fbuf, d4, fm4);
    // 17. global max feature
    fglobal_kernel<<<BSZ, 512>>>(fm4, fglob);
    // 18. nearest-neighbor upsample indices
    nearest_kernel<<<dim3(NV/128, BSZ), 128>>>(vertices, vp1, NV, NP1, near1);
    nearest_kernel<<<dim3(NV/128, BSZ), 128>>>(vertices, vp2, NV, NP2, near2);
    // 19. fuse (16384 x 1792)
    fuse_kernel<<<BSZ*NV, 256>>>(fm0, fm1, fm2, fm3, fm4, fglob, near1, near2, fuse);
    // 20-22. MLP head
    gemm128<true,true ><<<dim3(512/128, (BSZ*NV)/128), 256>>>(fuse, cw1, cb1, h1, BSZ*NV, 512, 1792);
    gemm128<true,true ><<<dim3(512/128, (BSZ*NV)/128), 256>>>(h1,   cw2, cb2, h2, BSZ*NV, 512, 512);
    head_kernel<<<(BSZ*NV)/16, 256>>>(h2, cw3, cb3, out);
}

// round 5
// speedup vs baseline: 1.1332x; 1.1332x over previous
#include <cuda_runtime.h>
#include <cuda_bf16.h>
#include <math.h>
#include <stdint.h>

#define BSZ 4
#define NV  4096
#define NP1 1024
#define NP2 256
#define KNN 32
typedef __nv_bfloat16 bf16;

// ---------------- scratch (device globals; no allocation allowed) ------------
__device__ int   g_nb1[BSZ*NV*KNN];
__device__ int   g_nb2[BSZ*NP1*KNN];
__device__ int   g_nb3[BSZ*NP2*KNN];
__device__ int   g_nbp[BSZ*NP1*4];
__device__ int   g_near1[BSZ*NV];
__device__ int   g_near2[BSZ*NV];
__device__ float g_fm0[BSZ*NV*128];
__device__ float g_fm1[BSZ*NV*128];
__device__ float g_f  [BSZ*NV*256];
__device__ float g_vp1[BSZ*NP1*3];
__device__ float g_fmp1[BSZ*NP1*128];
__device__ float g_fm2[BSZ*NP1*256];
__device__ float g_fm3[BSZ*NP1*256];
__device__ float g_vp2[BSZ*NP2*3];
__device__ float g_fmp2[BSZ*NP2*256];
__device__ float g_fm4[BSZ*NP2*512];
__device__ float g_fglob[BSZ*512];
__device__ float g_h2[BSZ*NV*512];
// bf16 split buffers for tensor-core head GEMMs
__device__ __align__(256) bf16 g_fusehi[BSZ*NV*1792];
__device__ __align__(256) bf16 g_fuselo[BSZ*NV*1792];
__device__ __align__(256) bf16 g_h1hi[BSZ*NV*512];
__device__ __align__(256) bf16 g_h1lo[BSZ*NV*512];
__device__ __align__(256) bf16 g_cw1hi[512*1792];
__device__ __align__(256) bf16 g_cw1lo[512*1792];
__device__ __align__(256) bf16 g_cw2hi[512*512];
__device__ __align__(256) bf16 g_cw2lo[512*512];

// ---------------- PTX helpers (arch-agnostic: sm_80-era instructions) --------
__device__ __forceinline__ uint32_t smem_u32(const void* p){
    uint32_t a;
    asm("{ .reg .u64 t; cvta.to.shared.u64 t, %1; cvt.u32.u64 %0, t; }" : "=r"(a) : "l"(p));
    return a;
}
#define CP_ASYNC16(dst, src) \
    asm volatile("cp.async.ca.shared.global [%0], [%1], 16;" :: "r"(dst), "l"(src) : "memory")
#define CP_COMMIT() asm volatile("cp.async.commit_group;" ::: "memory")
#define CP_WAIT(n)  asm volatile("cp.async.wait_group %0;" :: "n"(n) : "memory")
#define LDSM_X4(r, a) \
    asm volatile("ldmatrix.sync.aligned.m8n8.x4.shared.b16 {%0,%1,%2,%3}, [%4];" \
        : "=r"((r)[0]),"=r"((r)[1]),"=r"((r)[2]),"=r"((r)[3]) : "r"(a))
#define LDSM_X2(r, a) \
    asm volatile("ldmatrix.sync.aligned.m8n8.x2.shared.b16 {%0,%1}, [%2];" \
        : "=r"((r)[0]),"=r"((r)[1]) : "r"(a))
#define MMA_BF16(d, a, b) \
    asm volatile("mma.sync.aligned.m16n8k16.row.col.f32.bf16.bf16.f32 " \
        "{%0,%1,%2,%3}, {%4,%5,%6,%7}, {%8,%9}, {%0,%1,%2,%3};" \
        : "+f"((d)[0]),"+f"((d)[1]),"+f"((d)[2]),"+f"((d)[3]) \
        : "r"((a)[0]),"r"((a)[1]),"r"((a)[2]),"r"((a)[3]), "r"((b)[0]),"r"((b)[1]))

// ---------------- split fp32 -> bf16 hi/lo -----------------------------------
__global__ void split_kernel(const float* __restrict__ src,
                             bf16* __restrict__ hi, bf16* __restrict__ lo, int n)
{
    int i = blockIdx.x*256 + threadIdx.x;
    if (i < n) {
        float v = src[i];
        bf16 h = __float2bfloat16(v);
        hi[i] = h;
        lo[i] = __float2bfloat16(v - __bfloat162float(h));
    }
}

// ================= warp-MMA GEMM: C(128x128 tile) = A @ B^T + bias ===========
// A: (M,K) bf16 hi/lo row-major.  B: (N,K) bf16 hi/lo row-major.
// Split: D = Ah@Bh + Ah@Bl + Al@Bh  (fp32 accum in registers).
// smem: 2 stages x [Ah(16K) Al(16K) Bh(16K) Bl(16K)]; K chunk = 64 bf16
// (128B rows, SW128 swizzle), cp.async double-buffered.
#define MMA_SMEM_TOTAL (2*65536)
template<int KTOT, bool RELU, bool OUT_SPLIT>
__global__ __launch_bounds__(256, 1)
void mma_gemm(const bf16* __restrict__ Ahi, const bf16* __restrict__ Alo,
              const bf16* __restrict__ Bhi, const bf16* __restrict__ Blo,
              const float* __restrict__ bias, int Nstride,
              float* __restrict__ Cf, bf16* __restrict__ Chi, bf16* __restrict__ Clo)
{
    extern __shared__ __align__(1024) char smem[];
    const uint32_t sbase = smem_u32(smem);
    const int tid  = threadIdx.x;
    const int lane = tid & 31, warp = tid >> 5;
    const int m0 = blockIdx.y * 128, n0 = blockIdx.x * 128;
    const int wm = (warp >> 2) * 64, wn = (warp & 3) * 32;

    // loader geometry: 256 thr; per buffer 128 rows x 128B; thread -> 4 rows
    const int      lr0  = tid >> 3;          // 0..31
    const uint32_t lc16 = (tid & 7) * 16;    // byte col within 128B row
    const int      lcel = (tid & 7) * 8;     // bf16 elem col

    const bf16* srcs[4] = { Ahi + (size_t)m0*KTOT, Alo + (size_t)m0*KTOT,
                            Bhi + (size_t)n0*KTOT, Blo + (size_t)n0*KTOT };

    float acc[4][4][4];
#pragma unroll
    for (int mi=0;mi<4;mi++)
#pragma unroll
        for (int ni=0;ni<4;ni++)
#pragma unroll
            for (int q=0;q<4;q++) acc[mi][ni][q]=0.f;

    const int NCH = KTOT / 64;

    // prologue: chunk 0 -> stage 0
    {
        const size_t kb = lcel;
#pragma unroll
        for (int b=0;b<4;b++)
#pragma unroll
            for (int it=0;it<4;it++) {
                const int row = lr0 + it*32;
                const uint32_t dst = sbase + b*16384u + row*128u + (lc16 ^ ((row&7)<<4));
                CP_ASYNC16(dst, (const void*)(srcs[b] + (size_t)row*KTOT + kb));
            }
        CP_COMMIT();
    }

    // per-lane ldmatrix address components
    const int      arow_in = (lane & 7) + (lane & 8);
    const uint32_t abyte   = (lane & 16) ? 16u : 0u;
    const int      brow_in = lane & 7;
    const uint32_t bbyte   = (lane & 8) ? 16u : 0u;

    for (int i=0;i<NCH;i++) {
        if (i+1 < NCH) {
            const uint32_t sb = sbase + ((i+1)&1)*65536u;
            const size_t kb = (size_t)(i+1)*64 + lcel;
#pragma unroll
            for (int b=0;b<4;b++)
#pragma unroll
                for (int it=0;it<4;it++) {
                    const int row = lr0 + it*32;
                    const uint32_t dst = sb + b*16384u + row*128u + (lc16 ^ ((row&7)<<4));
                    CP_ASYNC16(dst, (const void*)(srcs[b] + (size_t)row*KTOT + kb));
                }
            CP_COMMIT();
            CP_WAIT(1);
        } else {
            CP_WAIT(0);
        }
        __syncthreads();

        const uint32_t sb = sbase + (i&1)*65536u;
#pragma unroll
        for (int kk=0;kk<4;kk++) {
            const uint32_t kbb = kk*32u;
            uint32_t ah[4][4], al[4][4], bhf[4][2], blf[4][2];
#pragma unroll
            for (int mi=0;mi<4;mi++) {
                const int row = wm + mi*16 + arow_in;
                const uint32_t off = row*128u + ((kbb + abyte) ^ ((row&7)<<4));
                LDSM_X4(ah[mi], sb + off);
                LDSM_X4(al[mi], sb + 16384u + off);
            }
#pragma unroll
            for (int ni=0;ni<4;ni++) {
                const int row = wn + ni*8 + brow_in;
                const uint32_t off = row*128u + ((kbb + bbyte) ^ ((row&7)<<4));
                LDSM_X2(bhf[ni], sb + 32768u + off);
                LDSM_X2(blf[ni], sb + 49152u + off);
            }
#pragma unroll
            for (int mi=0;mi<4;mi++)
#pragma unroll
                for (int ni=0;ni<4;ni++) {
                    MMA_BF16(acc[mi][ni], ah[mi], bhf[ni]);
                    MMA_BF16(acc[mi][ni], ah[mi], blf[ni]);
                    MMA_BF16(acc[mi][ni], al[mi], bhf[ni]);
                }
        }
        __syncthreads();
    }

    // epilogue: bias (+relu) -> global (fp32 or bf16 hi/lo split)
#pragma unroll
    for (int mi=0;mi<4;mi++) {
        const int r0g = m0 + wm + mi*16 + (lane>>2);
#pragma unroll
        for (int ni=0;ni<4;ni++) {
            const int col = n0 + wn + ni*8 + (lane&3)*2;
            const float b0 = bias[col], b1 = bias[col+1];
            float v0 = acc[mi][ni][0] + b0, v1 = acc[mi][ni][1] + b1;
            float v2 = acc[mi][ni][2] + b0, v3 = acc[mi][ni][3] + b1;
            if (RELU) {
                v0 = fmaxf(v0,0.f); v1 = fmaxf(v1,0.f);
                v2 = fmaxf(v2,0.f); v3 = fmaxf(v3,0.f);
            }
            const size_t g0 = (size_t)r0g*Nstride + col;
            const size_t g1 = (size_t)(r0g+8)*Nstride + col;
            if (OUT_SPLIT) {
                bf16 h0 = __float2bfloat16(v0), h1 = __float2bfloat16(v1);
                bf16 h2b = __float2bfloat16(v2), h3 = __float2bfloat16(v3);
                Chi[g0] = h0; Chi[g0+1] = h1;
                Chi[g1] = h2b; Chi[g1+1] = h3;
                Clo[g0]   = __float2bfloat16(v0 - __bfloat162float(h0));
                Clo[g0+1] = __float2bfloat16(v1 - __bfloat162float(h1));
                Clo[g1]   = __float2bfloat16(v2 - __bfloat162float(h2b));
                Clo[g1+1] = __float2bfloat16(v3 - __bfloat162float(h3));
            } else {
                float2 p0 = make_float2(v0, v1), p1 = make_float2(v2, v3);
                *(float2*)&Cf[g0] = p0;
                *(float2*)&Cf[g1] = p1;
            }
        }
    }
}

// ---------------- KNN: brute force, smem-tiled, insertion top-K --------------
template<int K>
__global__ void knn_kernel(const float* __restrict__ verts,
                           const int* __restrict__ qidx, // null => identity
                           int nq, int V, int* __restrict__ out)
{
    int b = blockIdx.y;
    int q = blockIdx.x * 128 + threadIdx.x;
    const float* vb = verts + (size_t)b * V * 3;
    bool active = q < nq;
    int self = -1;
    float qx=0.f, qy=0.f, qz=0.f, qa2=0.f;
    if (active) {
        self = qidx ? qidx[q] : q;
        qx = vb[self*3+0]; qy = vb[self*3+1]; qz = vb[self*3+2];
        qa2 = qx*qx + qy*qy + qz*qz;
    }
    float dk[K]; int ik[K];
#pragma unroll
    for (int i=0;i<K;i++){ dk[i]=3.4e38f; ik[i]=0; }
    float worst = 3.4e38f;

    __shared__ float4 sp[128];
    for (int t0=0; t0<V; t0+=128) {
        int j = t0 + threadIdx.x;
        float x = vb[j*3+0], y = vb[j*3+1], z = vb[j*3+2];
        sp[threadIdx.x] = make_float4(x,y,z, x*x+y*y+z*z);
        __syncthreads();
        if (active) {
            for (int jj=0; jj<128; jj++) {
                float4 p = sp[jj];
                float d = qa2 + p.w - 2.0f*(qx*p.x + qy*p.y + qz*p.z);
                int gj = t0 + jj;
                if (gj != self && d < worst) {
                    int pos = K-1;
                    while (pos > 0 && dk[pos-1] > d) {
                        dk[pos]=dk[pos-1]; ik[pos]=ik[pos-1]; --pos;
                    }
                    dk[pos]=d; ik[pos]=gj;
                    worst = dk[K-1];
                }
            }
        }
        __syncthreads();
    }
    if (active) {
        int* o = out + ((size_t)b*nq + q)*K;
#pragma unroll
        for (int i=0;i<K;i++) o[i]=ik[i];
    }
}

// ---------------- conv_surface (fm0) ----------------------------------------
__global__ void conv_surface_kernel(const float* __restrict__ verts,
                                    const int* __restrict__ nb,
                                    const float* __restrict__ dir0,
                                    float* __restrict__ fm0)
{
    int bv = blockIdx.x;
    int b = bv >> 12, v = bv & (NV-1);
    const float* vb = verts + (size_t)b*NV*3;
    __shared__ float sdx[KNN], sdy[KNN], sdz[KNN];
    int t = threadIdx.x;
    float cx = vb[v*3+0], cy = vb[v*3+1], cz = vb[v*3+2];
    if (t < KNN) {
        int j = nb[(size_t)bv*KNN + t];
        float dx = vb[j*3+0]-cx, dy = vb[j*3+1]-cy, dz = vb[j*3+2]-cz;
        float n = sqrtf(dx*dx+dy*dy+dz*dz);
        float inv = 1.0f / fmaxf(n, 1e-12f);
        sdx[t]=dx*inv; sdy[t]=dy*inv; sdz[t]=dz*inv;
    }
    __syncthreads();
    int k = t;
    float d0 = dir0[k], d1 = dir0[128+k], d2 = dir0[256+k];
    float n = sqrtf(d0*d0+d1*d1+d2*d2);
    float inv = 1.0f / fmaxf(n, 1e-12f);
    d0*=inv; d1*=inv; d2*=inv;
    float m = 0.0f;
#pragma unroll
    for (int j=0;j<KNN;j++)
        m = fmaxf(m, sdx[j]*d0 + sdy[j]*d1 + sdz[j]*d2);
    fm0[(size_t)bv*128 + k] = m;
}

// ---------------- conv_layer epilogue ----------------------------------------
template<int COUT, bool RELU>
__global__ void conv_layer_kernel(const float* __restrict__ verts, int V,
                                  const int* __restrict__ nb,
                                  const float* __restrict__ f,
                                  const float* __restrict__ dirs,
                                  float* __restrict__ out)
{
    int bv = blockIdx.x;
    int b = bv / V, v = bv - b*V;
    const float* vb = verts + (size_t)b*V*3;
    __shared__ float sdx[KNN], sdy[KNN], sdz[KNN];
    __shared__ int   si[KNN];
    int t = threadIdx.x;
    float cx = vb[v*3+0], cy = vb[v*3+1], cz = vb[v*3+2];
    if (t < KNN) {
        int j = nb[(size_t)bv*KNN + t];
        si[t] = j;
        float dx = vb[j*3+0]-cx, dy = vb[j*3+1]-cy, dz = vb[j*3+2]-cz;
        float n = sqrtf(dx*dx+dy*dy+dz*dz);
        float inv = 1.0f / fmaxf(n, 1e-12f);
        sdx[t]=dx*inv; sdy[t]=dy*inv; sdz[t]=dz*inv;
    }
    __syncthreads();
    const float* fb = f + (size_t)b*V*(2*COUT);
    for (int co = t; co < COUT; co += blockDim.x) {
        float d0 = dirs[co], d1 = dirs[COUT+co], d2 = dirs[2*COUT+co];
        float n = sqrtf(d0*d0+d1*d1+d2*d2);
        float inv = 1.0f / fmaxf(n, 1e-12f);
        d0*=inv; d1*=inv; d2*=inv;
        float m = -3.4e38f;
#pragma unroll 8
        for (int j=0;j<KNN;j++) {
            float th = fmaxf(sdx[j]*d0 + sdy[j]*d1 + sdz[j]*d2, 0.0f);
            float val = th * fb[(size_t)si[j]*(2*COUT) + COUT + co];
            m = fmaxf(m, val);
        }
        float r = fb[(size_t)v*(2*COUT) + co] + m;
        out[((size_t)b*V+v)*COUT + co] = RELU ? fmaxf(r, 0.0f) : r;
    }
}

// ---------------- pool ------------------------------------------------------
__global__ void pool_kernel(const float* __restrict__ verts,
                            const float* __restrict__ fm,
                            int V, int C,
                            const int* __restrict__ sidx,
                            const int* __restrict__ nb4, int ns,
                            float* __restrict__ vout, float* __restrict__ fout)
{
    int bq = blockIdx.x;
    int b = bq / ns, q = bq - b*ns;
    int t = threadIdx.x;
    int sv = sidx[q];
    if (t < 3) vout[(size_t)bq*3 + t] = verts[((size_t)b*V + sv)*3 + t];
    const int* nbq = nb4 + (size_t)bq*4;
    int j0=nbq[0], j1=nbq[1], j2=nbq[2], j3=nbq[3];
    const float* fb = fm + (size_t)b*V*C;
    for (int c=t; c<C; c+=blockDim.x) {
        float m = fmaxf(fmaxf(fb[(size_t)j0*C+c], fb[(size_t)j1*C+c]),
                        fmaxf(fb[(size_t)j2*C+c], fb[(size_t)j3*C+c]));
        fout[(size_t)bq*C + c] = m;
    }
}

// ---------------- nearest ---------------------------------------------------
__global__ void nearest_kernel(const float* __restrict__ verts,
                               const float* __restrict__ src,
                               int V, int S, int* __restrict__ out)
{
    int b = blockIdx.y;
    int q = blockIdx.x * 128 + threadIdx.x;
    const float* vb = verts + (size_t)b*V*3;
    const float* sb = src + (size_t)b*S*3;
    float qx = vb[q*3+0], qy = vb[q*3+1], qz = vb[q*3+2];
    float qa2 = qx*qx + qy*qy + qz*qz;
    float best = 3.4e38f; int bi = 0;
    __shared__ float4 sp[128];
    for (int t0=0; t0<S; t0+=128) {
        int j = t0 + threadIdx.x;
        float x = sb[j*3+0], y = sb[j*3+1], z = sb[j*3+2];
        sp[threadIdx.x] = make_float4(x,y,z, x*x+y*y+z*z);
        __syncthreads();
        for (int jj=0; jj<128; jj++) {
            float4 p = sp[jj];
            float d = qa2 + p.w - 2.0f*(qx*p.x + qy*p.y + qz*p.z);
            if (d < best) { best = d; bi = t0+jj; }
        }
        __syncthreads();
    }
    out[(size_t)b*V + q] = bi;
}

// ---------------- global feature --------------------------------------------
__global__ void fglobal_kernel(const float* __restrict__ fm4, float* __restrict__ g)
{
    int b = blockIdx.x, c = threadIdx.x;
    float m = -3.4e38f;
    for (int v=0; v<NP2; v++) m = fmaxf(m, fm4[((size_t)b*NP2+v)*512 + c]);
    g[(size_t)b*512 + c] = m;
}

// ---------------- fuse assembly -> bf16 hi/lo ---------------------------------
__global__ void fuse_kernel(const float* __restrict__ fm0, const float* __restrict__ fm1,
                            const float* __restrict__ fm2, const float* __restrict__ fm3,
                            const float* __restrict__ fm4, const float* __restrict__ fg,
                            const int* __restrict__ near1, const int* __restrict__ near2,
                            bf16* __restrict__ fhi, bf16* __restrict__ flo)
{
    int bv = blockIdx.x;
    int b = bv >> 12;
    int n1 = near1[bv], n2 = near2[bv];
    size_t o = (size_t)bv*1792;
    for (int c = threadIdx.x; c < 1792; c += blockDim.x) {
        float val;
        if (c < 128)        val = fm0[(size_t)bv*128 + c];
        else if (c < 256)   val = fm1[(size_t)bv*128 + (c-128)];
        else if (c < 512)   val = fm2[((size_t)b*NP1+n1)*256 + (c-256)];
        else if (c < 768)   val = fm3[((size_t)b*NP1+n1)*256 + (c-512)];
        else if (c < 1280)  val = fm4[((size_t)b*NP2+n2)*512 + (c-768)];
        else                val = fg [(size_t)b*512 + (c-1280)];
        bf16 h = __float2bfloat16(val);
        fhi[o+c] = h;
        flo[o+c] = __float2bfloat16(val - __bfloat162float(h));
    }
}

// ---------------- scalar SGEMM (for small f-layer GEMMs) ---------------------
#define SMS 132
template<bool BT, bool RELU>
__global__ __launch_bounds__(256, 2)
void gemm128(const float* __restrict__ A, const float* __restrict__ B,
             const float* __restrict__ bias, float* __restrict__ C,
             int M, int N, int K)
{
    __shared__ __align__(16) float As[2][8*SMS];
    __shared__ __align__(16) float Bs[2][8*SMS];
    const int tid = threadIdx.x;
    const int tx = tid & 15;
    const int ty = tid >> 4;
    const int m0 = blockIdx.y * 128;
    const int n0 = blockIdx.x * 128;

    const int arow = tid >> 1;
    const int akp  = (tid & 1) * 4;
    const float* Aptr = A + (size_t)(m0 + arow) * K + akp;

    const float* Bptr;
    int bkk = 0, bn4 = 0;
    if (BT) {
        Bptr = B + (size_t)(n0 + arow) * K + akp;
    } else {
        bkk = tid >> 5; bn4 = (tid & 31) * 4;
        Bptr = B + (size_t)bkk * N + n0 + bn4;
    }

    float acc[8][8];
#pragma unroll
    for (int i=0;i<8;i++)
#pragma unroll
        for (int j=0;j<8;j++) acc[i][j]=0.f;

    const int NT = K >> 3;

    float4 areg = *(const float4*)Aptr;
    float4 breg = *(const float4*)Bptr;
    As[0][(akp+0)*SMS+arow]=areg.x;
    As[0][(akp+1)*SMS+arow]=areg.y;
    As[0][(akp+2)*SMS+arow]=areg.z;
    As[0][(akp+3)*SMS+arow]=areg.w;
    if (BT) {
        Bs[0][(akp+0)*SMS+arow]=breg.x;
        Bs[0][(akp+1)*SMS+arow]=breg.y;
        Bs[0][(akp+2)*SMS+arow]=breg.z;
        Bs[0][(akp+3)*SMS+arow]=breg.w;
    } else {
        *(float4*)&Bs[0][bkk*SMS+bn4] = breg;
    }
    __syncthreads();

    for (int kt=0; kt<NT; kt++) {
        const int cur = kt & 1;
        if (kt+1 < NT) {
            areg = *(const float4*)(Aptr + (size_t)(kt+1)*8);
            if (BT) breg = *(const float4*)(Bptr + (size_t)(kt+1)*8);
            else    breg = *(const float4*)(Bptr + (size_t)(kt+1)*8*N);
        }
        const float* as = As[cur];
        const float* bs = Bs[cur];
#pragma unroll
        for (int kk=0; kk<8; kk++) {
            float4 a0 = *(const float4*)&as[kk*SMS + ty*4];
            float4 a1 = *(const float4*)&as[kk*SMS + 64 + ty*4];
            float4 b0 = *(const float4*)&bs[kk*SMS + tx*4];
            float4 b1 = *(const float4*)&bs[kk*SMS + 64 + tx*4];
            float av[8] = {a0.x,a0.y,a0.z,a0.w,a1.x,a1.y,a1.z,a1.w};
            float bv[8] = {b0.x,b0.y,b0.z,b0.w,b1.x,b1.y,b1.z,b1.w};
#pragma unroll
            for (int i=0;i<8;i++)
#pragma unroll
                for (int j=0;j<8;j++)
                    acc[i][j] += av[i]*bv[j];
        }
        if (kt+1 < NT) {
            const int nxt = cur ^ 1;
            As[nxt][(akp+0)*SMS+arow]=areg.x;
            As[nxt][(akp+1)*SMS+arow]=areg.y;
            As[nxt][(akp+2)*SMS+arow]=areg.z;
            As[nxt][(akp+3)*SMS+arow]=areg.w;
            if (BT) {
                Bs[nxt][(akp+0)*SMS+arow]=breg.x;
                Bs[nxt][(akp+1)*SMS+arow]=breg.y;
                Bs[nxt][(akp+2)*SMS+arow]=breg.z;
                Bs[nxt][(akp+3)*SMS+arow]=breg.w;
            } else {
                *(float4*)&Bs[nxt][bkk*SMS+bn4] = breg;
            }
        }
        __syncthreads();
    }

#pragma unroll
    for (int ih=0; ih<2; ih++)
#pragma unroll
    for (int ii=0; ii<4; ii++) {
        const int i = ih*4 + ii;
        const int gm = m0 + ih*64 + ty*4 + ii;
        if (gm >= M) continue;
        float* crow = C + (size_t)gm*N + n0;
#pragma unroll
        for (int jh=0; jh<2; jh++) {
            const int cb = jh*64 + tx*4;
            if (n0 + cb >= N) continue;
            float4 bv = *(const float4*)&bias[n0 + cb];
            float4 v;
            v.x = acc[i][jh*4+0] + bv.x;
            v.y = acc[i][jh*4+1] + bv.y;
            v.z = acc[i][jh*4+2] + bv.z;
            v.w = acc[i][jh*4+3] + bv.w;
            if (RELU) {
                v.x = fmaxf(v.x, 0.f); v.y = fmaxf(v.y, 0.f);
                v.z = fmaxf(v.z, 0.f); v.w = fmaxf(v.w, 0.f);
            }
            *(float4*)&crow[cb] = v;
        }
    }
}

// ---------------- head: out(16 rows x 13) = h2 @ cw3^T + cb3 ----------------
__global__ void head_kernel(const float* __restrict__ h2,
                            const float* __restrict__ cw3,
                            const float* __restrict__ cb3,
                            float* __restrict__ out)
{
    __shared__ float sh[16][512];
    __shared__ float sw[13*513];
    const int tid = threadIdx.x;
    const int r = tid >> 4, c = tid & 15;
    const int row0 = blockIdx.x * 16;
    for (int i = tid; i < 16*512; i += 256)
        sh[i>>9][i&511] = h2[(size_t)row0*512 + i];
    for (int i = tid; i < 13*512; i += 256)
        sw[(i>>9)*513 + (i&511)] = cw3[i];
    __syncthreads();
    if (c < 13) {
        float acc = cb3[c];
        const float* w = &sw[c*513];
        const float* hrow = sh[r];
#pragma unroll 8
        for (int k=0;k<512;k++) acc += hrow[k]*w[k];
        out[(size_t)(row0+r)*13 + c] = acc;
    }
}

// -----------------------------------------------------------------------------
static void* sym_addr(const void* symbol) {
    void* p = nullptr;
    cudaGetSymbolAddress(&p, symbol);
    return p;
}

extern "C" void kernel_launch(void* const* d_in, const int* in_sizes, int n_in,
                              void* d_out, int out_size)
{
    (void)in_sizes; (void)n_in; (void)out_size;
    const float* vertices = (const float*)d_in[0];
    const int*   sidx1    = (const int*)  d_in[1];
    const int*   sidx2    = (const int*)  d_in[2];
    const float* dir0     = (const float*)d_in[3];
    const float* w1 = (const float*)d_in[4];  const float* b1 = (const float*)d_in[5];  const float* d1 = (const float*)d_in[6];
    const float* w2 = (const float*)d_in[7];  const float* b2 = (const float*)d_in[8];  const float* d2 = (const float*)d_in[9];
    const float* w3 = (const float*)d_in[10]; const float* b3 = (const float*)d_in[11]; const float* d3 = (const float*)d_in[12];
    const float* w4 = (const float*)d_in[13]; const float* b4 = (const float*)d_in[14]; const float* d4 = (const float*)d_in[15];
    const float* cw1 = (const float*)d_in[16]; const float* cb1 = (const float*)d_in[17];
    const float* cw2 = (const float*)d_in[18]; const float* cb2 = (const float*)d_in[19];
    const float* cw3 = (const float*)d_in[20]; const float* cb3 = (const float*)d_in[21];
    float* out = (float*)d_out;

    int*   nb1   = (int*)  sym_addr(g_nb1);
    int*   nb2   = (int*)  sym_addr(g_nb2);
    int*   nb3   = (int*)  sym_addr(g_nb3);
    int*   nbp   = (int*)  sym_addr(g_nbp);
    int*   near1 = (int*)  sym_addr(g_near1);
    int*   near2 = (int*)  sym_addr(g_near2);
    float* fm0   = (float*)sym_addr(g_fm0);
    float* fm1   = (float*)sym_addr(g_fm1);
    float* fbuf  = (float*)sym_addr(g_f);
    float* vp1   = (float*)sym_addr(g_vp1);
    float* fmp1  = (float*)sym_addr(g_fmp1);
    float* fm2   = (float*)sym_addr(g_fm2);
    float* fm3   = (float*)sym_addr(g_fm3);
    float* vp2   = (float*)sym_addr(g_vp2);
    float* fmp2  = (float*)sym_addr(g_fmp2);
    float* fm4   = (float*)sym_addr(g_fm4);
    float* fglob = (float*)sym_addr(g_fglob);
    float* h2    = (float*)sym_addr(g_h2);
    bf16* fusehi = (bf16*)sym_addr(g_fusehi);
    bf16* fuselo = (bf16*)sym_addr(g_fuselo);
    bf16* h1hi   = (bf16*)sym_addr(g_h1hi);
    bf16* h1lo   = (bf16*)sym_addr(g_h1lo);
    bf16* cw1hi  = (bf16*)sym_addr(g_cw1hi);
    bf16* cw1lo  = (bf16*)sym_addr(g_cw1lo);
    bf16* cw2hi  = (bf16*)sym_addr(g_cw2hi);
    bf16* cw2lo  = (bf16*)sym_addr(g_cw2lo);

    cudaFuncSetAttribute(mma_gemm<1792,true,true>,  cudaFuncAttributeMaxDynamicSharedMemorySize, MMA_SMEM_TOTAL);
    cudaFuncSetAttribute(mma_gemm<512,true,false>,  cudaFuncAttributeMaxDynamicSharedMemorySize, MMA_SMEM_TOTAL);

    // weight splits (independent, run first)
    split_kernel<<<(512*1792+255)/256, 256>>>(cw1, cw1hi, cw1lo, 512*1792);
    split_kernel<<<(512*512+255)/256, 256>>>(cw2, cw2hi, cw2lo, 512*512);

    // 1. full-res KNN(32)
    knn_kernel<KNN><<<dim3(NV/128, BSZ), 128>>>(vertices, nullptr, NV, NV, nb1);
    // 2. fm0 = conv_surface
    conv_surface_kernel<<<BSZ*NV, 128>>>(vertices, nb1, dir0, fm0);
    // 3-4. fm1
    gemm128<false,false><<<dim3(2, (BSZ*NV)/128), 256>>>(fm0, w1, b1, fbuf, BSZ*NV, 256, 128);
    conv_layer_kernel<128,true><<<BSZ*NV, 128>>>(vertices, NV, nb1, fbuf, d1, fm1);
    // 5-6. pool1
    knn_kernel<4><<<dim3(NP1/128, BSZ), 128>>>(vertices, sidx1, NP1, NV, nbp);
    pool_kernel<<<BSZ*NP1, 128>>>(vertices, fm1, NV, 128, sidx1, nbp, NP1, vp1, fmp1);
    // 7. KNN level 1
    knn_kernel<KNN><<<dim3(NP1/128, BSZ), 128>>>(vp1, nullptr, NP1, NP1, nb2);
    // 8-9. fm2
    gemm128<false,false><<<dim3(4, (BSZ*NP1)/128), 256>>>(fmp1, w2, b2, fbuf, BSZ*NP1, 512, 128);
    conv_layer_kernel<256,true><<<BSZ*NP1, 256>>>(vp1, NP1, nb2, fbuf, d2, fm2);
    // 10-11. fm3
    gemm128<false,false><<<dim3(4, (BSZ*NP1)/128), 256>>>(fm2, w3, b3, fbuf, BSZ*NP1, 512, 256);
    conv_layer_kernel<256,true><<<BSZ*NP1, 256>>>(vp1, NP1, nb2, fbuf, d3, fm3);
    // 12-13. pool2
    knn_kernel<4><<<dim3(NP2/128, BSZ), 128>>>(vp1, sidx2, NP2, NP1, nbp);
    pool_kernel<<<BSZ*NP2, 256>>>(vp1, fm3, NP1, 256, sidx2, nbp, NP2, vp2, fmp2);
    // 14. KNN level 2
    knn_kernel<KNN><<<dim3(NP2/128, BSZ), 128>>>(vp2, nullptr, NP2, NP2, nb3);
    // 15-16. fm4
    gemm128<false,false><<<dim3(8, (BSZ*NP2)/128), 256>>>(fmp2, w4, b4, fbuf, BSZ*NP2, 1024, 256);
    conv_layer_kernel<512,false><<<BSZ*NP2, 256>>>(vp2, NP2, nb3, fbuf, d4, fm4);
    // 17. global max feature
    fglobal_kernel<<<BSZ, 512>>>(fm4, fglob);
    // 18. nearest upsample indices
    nearest_kernel<<<dim3(NV/128, BSZ), 128>>>(vertices, vp1, NV, NP1, near1);
    nearest_kernel<<<dim3(NV/128, BSZ), 128>>>(vertices, vp2, NV, NP2, near2);
    // 19. fuse -> bf16 hi/lo directly
    fuse_kernel<<<BSZ*NV, 256>>>(fm0, fm1, fm2, fm3, fm4, fglob, near1, near2, fusehi, fuselo);
    // 20. h1 = relu(fuse @ cw1^T + cb1)  [warp-MMA split bf16, emits bf16 hi/lo]
    mma_gemm<1792,true,true><<<dim3(4, (BSZ*NV)/128), 256, MMA_SMEM_TOTAL>>>(
        fusehi, fuselo, cw1hi, cw1lo, cb1, 512, nullptr, h1hi, h1lo);
    // 21. h2 = relu(h1 @ cw2^T + cb2)  [warp-MMA, emits fp32]
    mma_gemm<512,true,false><<<dim3(4, (BSZ*NV)/128), 256, MMA_SMEM_TOTAL>>>(
        h1hi, h1lo, cw2hi, cw2lo, cb2, 512, h2, nullptr, nullptr);
    // 22. logits
    head_kernel<<<(BSZ*NV)/16, 256>>>(h2, cw3, cb3, out);
}

// round 6
// speedup vs baseline: 2.1186x; 1.8696x over previous
#include <cuda_runtime.h>
#include <cuda_bf16.h>
#include <math.h>
#include <stdint.h>

#define BSZ 4
#define NV  4096
#define NP1 1024
#define NP2 256
#define KNN 32
typedef __nv_bfloat16 bf16;

// ---------------- scratch (device globals; no allocation allowed) ------------
__device__ int   g_nb1[BSZ*NV*KNN];
__device__ int   g_nb2[BSZ*NP1*KNN];
__device__ int   g_nb3[BSZ*NP2*KNN];
__device__ int   g_nbp[BSZ*NP1*4];
__device__ int   g_near1[BSZ*NV];
__device__ int   g_near2[BSZ*NV];
__device__ float g_fm0[BSZ*NV*128];
__device__ float g_fm1[BSZ*NV*128];
__device__ float g_f  [BSZ*NV*256];
__device__ float g_vp1[BSZ*NP1*3];
__device__ float g_fmp1[BSZ*NP1*128];
__device__ float g_fm2[BSZ*NP1*256];
__device__ float g_fm3[BSZ*NP1*256];
__device__ float g_vp2[BSZ*NP2*3];
__device__ float g_fmp2[BSZ*NP2*256];
__device__ float g_fm4[BSZ*NP2*512];
__device__ float g_fglob[BSZ*512];
__device__ float g_h2[BSZ*NV*512];
// bf16 split buffers for tensor-core head GEMMs
__device__ __align__(256) bf16 g_fusehi[BSZ*NV*1792];
__device__ __align__(256) bf16 g_fuselo[BSZ*NV*1792];
__device__ __align__(256) bf16 g_h1hi[BSZ*NV*512];
__device__ __align__(256) bf16 g_h1lo[BSZ*NV*512];
__device__ __align__(256) bf16 g_cw1hi[512*1792];
__device__ __align__(256) bf16 g_cw1lo[512*1792];
__device__ __align__(256) bf16 g_cw2hi[512*512];
__device__ __align__(256) bf16 g_cw2lo[512*512];

// ---------------- PTX helpers (arch-agnostic: sm_80-era instructions) --------
__device__ __forceinline__ uint32_t smem_u32(const void* p){
    uint32_t a;
    asm("{ .reg .u64 t; cvta.to.shared.u64 t, %1; cvt.u32.u64 %0, t; }" : "=r"(a) : "l"(p));
    return a;
}
#define CP_ASYNC16(dst, src) \
    asm volatile("cp.async.ca.shared.global [%0], [%1], 16;" :: "r"(dst), "l"(src) : "memory")
#define CP_COMMIT() asm volatile("cp.async.commit_group;" ::: "memory")
#define CP_WAIT(n)  asm volatile("cp.async.wait_group %0;" :: "n"(n) : "memory")
#define LDSM_X4(r, a) \
    asm volatile("ldmatrix.sync.aligned.m8n8.x4.shared.b16 {%0,%1,%2,%3}, [%4];" \
        : "=r"((r)[0]),"=r"((r)[1]),"=r"((r)[2]),"=r"((r)[3]) : "r"(a))
#define LDSM_X2(r, a) \
    asm volatile("ldmatrix.sync.aligned.m8n8.x2.shared.b16 {%0,%1}, [%2];" \
        : "=r"((r)[0]),"=r"((r)[1]) : "r"(a))
#define MMA_BF16(d, a, b) \
    asm volatile("mma.sync.aligned.m16n8k16.row.col.f32.bf16.bf16.f32 " \
        "{%0,%1,%2,%3}, {%4,%5,%6,%7}, {%8,%9}, {%0,%1,%2,%3};" \
        : "+f"((d)[0]),"+f"((d)[1]),"+f"((d)[2]),"+f"((d)[3]) \
        : "r"((a)[0]),"r"((a)[1]),"r"((a)[2]),"r"((a)[3]), "r"((b)[0]),"r"((b)[1]))

// ---------------- split fp32 -> bf16 hi/lo -----------------------------------
__global__ void split_kernel(const float* __restrict__ src,
                             bf16* __restrict__ hi, bf16* __restrict__ lo, int n)
{
    int i = blockIdx.x*256 + threadIdx.x;
    if (i < n) {
        float v = src[i];
        bf16 h = __float2bfloat16(v);
        hi[i] = h;
        lo[i] = __float2bfloat16(v - __bfloat162float(h));
    }
}

// ================= warp-MMA GEMM: C(128x128 tile) = A @ B^T + bias ===========
#define MMA_SMEM_TOTAL (2*65536)
template<int KTOT, bool RELU, bool OUT_SPLIT>
__global__ __launch_bounds__(256, 1)
void mma_gemm(const bf16* __restrict__ Ahi, const bf16* __restrict__ Alo,
              const bf16* __restrict__ Bhi, const bf16* __restrict__ Blo,
              const float* __restrict__ bias, int Nstride,
              float* __restrict__ Cf, bf16* __restrict__ Chi, bf16* __restrict__ Clo)
{
    extern __shared__ __align__(1024) char smem[];
    const uint32_t sbase = smem_u32(smem);
    const int tid  = threadIdx.x;
    const int lane = tid & 31, warp = tid >> 5;
    const int m0 = blockIdx.y * 128, n0 = blockIdx.x * 128;
    const int wm = (warp >> 2) * 64, wn = (warp & 3) * 32;

    const int      lr0  = tid >> 3;
    const uint32_t lc16 = (tid & 7) * 16;
    const int      lcel = (tid & 7) * 8;

    const bf16* srcs[4] = { Ahi + (size_t)m0*KTOT, Alo + (size_t)m0*KTOT,
                            Bhi + (size_t)n0*KTOT, Blo + (size_t)n0*KTOT };

    float acc[4][4][4];
#pragma unroll
    for (int mi=0;mi<4;mi++)
#pragma unroll
        for (int ni=0;ni<4;ni++)
#pragma unroll
            for (int q=0;q<4;q++) acc[mi][ni][q]=0.f;

    const int NCH = KTOT / 64;

    {
        const size_t kb = lcel;
#pragma unroll
        for (int b=0;b<4;b++)
#pragma unroll
            for (int it=0;it<4;it++) {
                const int row = lr0 + it*32;
                const uint32_t dst = sbase + b*16384u + row*128u + (lc16 ^ ((row&7)<<4));
                CP_ASYNC16(dst, (const void*)(srcs[b] + (size_t)row*KTOT + kb));
            }
        CP_COMMIT();
    }

    const int      arow_in = (lane & 7) + (lane & 8);
    const uint32_t abyte   = (lane & 16) ? 16u : 0u;
    const int      brow_in = lane & 7;
    const uint32_t bbyte   = (lane & 8) ? 16u : 0u;

    for (int i=0;i<NCH;i++) {
        if (i+1 < NCH) {
            const uint32_t sb = sbase + ((i+1)&1)*65536u;
            const size_t kb = (size_t)(i+1)*64 + lcel;
#pragma unroll
            for (int b=0;b<4;b++)
#pragma unroll
                for (int it=0;it<4;it++) {
                    const int row = lr0 + it*32;
                    const uint32_t dst = sb + b*16384u + row*128u + (lc16 ^ ((row&7)<<4));
                    CP_ASYNC16(dst, (const void*)(srcs[b] + (size_t)row*KTOT + kb));
                }
            CP_COMMIT();
            CP_WAIT(1);
        } else {
            CP_WAIT(0);
        }
        __syncthreads();

        const uint32_t sb = sbase + (i&1)*65536u;
#pragma unroll
        for (int kk=0;kk<4;kk++) {
            const uint32_t kbb = kk*32u;
            uint32_t ah[4][4], al[4][4], bhf[4][2], blf[4][2];
#pragma unroll
            for (int mi=0;mi<4;mi++) {
                const int row = wm + mi*16 + arow_in;
                const uint32_t off = row*128u + ((kbb + abyte) ^ ((row&7)<<4));
                LDSM_X4(ah[mi], sb + off);
                LDSM_X4(al[mi], sb + 16384u + off);
            }
#pragma unroll
            for (int ni=0;ni<4;ni++) {
                const int row = wn + ni*8 + brow_in;
                const uint32_t off = row*128u + ((kbb + bbyte) ^ ((row&7)<<4));
                LDSM_X2(bhf[ni], sb + 32768u + off);
                LDSM_X2(blf[ni], sb + 49152u + off);
            }
#pragma unroll
            for (int mi=0;mi<4;mi++)
#pragma unroll
                for (int ni=0;ni<4;ni++) {
                    MMA_BF16(acc[mi][ni], ah[mi], bhf[ni]);
                    MMA_BF16(acc[mi][ni], ah[mi], blf[ni]);
                    MMA_BF16(acc[mi][ni], al[mi], bhf[ni]);
                }
        }
        __syncthreads();
    }

#pragma unroll
    for (int mi=0;mi<4;mi++) {
        const int r0g = m0 + wm + mi*16 + (lane>>2);
#pragma unroll
        for (int ni=0;ni<4;ni++) {
            const int col = n0 + wn + ni*8 + (lane&3)*2;
            const float b0 = bias[col], b1 = bias[col+1];
            float v0 = acc[mi][ni][0] + b0, v1 = acc[mi][ni][1] + b1;
            float v2 = acc[mi][ni][2] + b0, v3 = acc[mi][ni][3] + b1;
            if (RELU) {
                v0 = fmaxf(v0,0.f); v1 = fmaxf(v1,0.f);
                v2 = fmaxf(v2,0.f); v3 = fmaxf(v3,0.f);
            }
            const size_t g0 = (size_t)r0g*Nstride + col;
            const size_t g1 = (size_t)(r0g+8)*Nstride + col;
            if (OUT_SPLIT) {
                bf16 h0 = __float2bfloat16(v0), h1 = __float2bfloat16(v1);
                bf16 h2b = __float2bfloat16(v2), h3 = __float2bfloat16(v3);
                Chi[g0] = h0; Chi[g0+1] = h1;
                Chi[g1] = h2b; Chi[g1+1] = h3;
                Clo[g0]   = __float2bfloat16(v0 - __bfloat162float(h0));
                Clo[g0+1] = __float2bfloat16(v1 - __bfloat162float(h1));
                Clo[g1]   = __float2bfloat16(v2 - __bfloat162float(h2b));
                Clo[g1+1] = __float2bfloat16(v3 - __bfloat162float(h3));
            } else {
                float2 p0 = make_float2(v0, v1), p1 = make_float2(v2, v3);
                *(float2*)&Cf[g0] = p0;
                *(float2*)&Cf[g1] = p1;
            }
        }
    }
}

// ---------------- KNN: brute force, branch-free register top-K ---------------
// Unsorted K-buffer + tracked max; all indices static after unroll (no local
// memory). Neighbor ORDER is irrelevant downstream (max-reductions only);
// kept SET identical to sorted insertion (strict d<worst gate).
template<int K>
__global__ void knn_kernel(const float* __restrict__ verts,
                           const int* __restrict__ qidx, // null => identity
                           int nq, int V, int* __restrict__ out)
{
    int b = blockIdx.y;
    int q = blockIdx.x * 128 + threadIdx.x;
    const float* vb = verts + (size_t)b * V * 3;
    bool active = q < nq;
    int self = -1;
    float qx=0.f, qy=0.f, qz=0.f, qa2=0.f;
    if (active) {
        self = qidx ? qidx[q] : q;
        qx = vb[self*3+0]; qy = vb[self*3+1]; qz = vb[self*3+2];
        qa2 = qx*qx + qy*qy + qz*qz;
    }
    float dk[K]; int ik[K];
#pragma unroll
    for (int i=0;i<K;i++){ dk[i]=3.4e38f; ik[i]=0; }
    float worst = 3.4e38f;
    int   wpos  = 0;

    __shared__ float4 sp[128];
    for (int t0=0; t0<V; t0+=128) {
        int j = t0 + threadIdx.x;   // V is a multiple of 128 always
        float x = vb[j*3+0], y = vb[j*3+1], z = vb[j*3+2];
        sp[threadIdx.x] = make_float4(x,y,z, x*x+y*y+z*z);
        __syncthreads();
        if (active) {
#pragma unroll 4
            for (int jj=0; jj<128; jj++) {
                float4 p = sp[jj];
                float d = qa2 + p.w - 2.0f*(qx*p.x + qy*p.y + qz*p.z);
                int gj = t0 + jj;
                if (d < worst && gj != self) {
                    float w = -3.4e38f; int wp = 0;
#pragma unroll
                    for (int i=0;i<K;i++) {
                        if (i == wpos) { dk[i] = d; ik[i] = gj; }
                        if (dk[i] > w) { w = dk[i]; wp = i; }
                    }
                    worst = w; wpos = wp;
                }
            }
        }
        __syncthreads();
    }
    if (active) {
        int* o = out + ((size_t)b*nq + q)*K;
#pragma unroll
        for (int i=0;i<K;i++) o[i]=ik[i];
    }
}

// ---------------- conv_surface (fm0) ----------------------------------------
__global__ void conv_surface_kernel(const float* __restrict__ verts,
                                    const int* __restrict__ nb,
                                    const float* __restrict__ dir0,
                                    float* __restrict__ fm0)
{
    int bv = blockIdx.x;
    int b = bv >> 12, v = bv & (NV-1);
    const float* vb = verts + (size_t)b*NV*3;
    __shared__ float sdx[KNN], sdy[KNN], sdz[KNN];
    int t = threadIdx.x;
    float cx = vb[v*3+0], cy = vb[v*3+1], cz = vb[v*3+2];
    if (t < KNN) {
        int j = nb[(size_t)bv*KNN + t];
        float dx = vb[j*3+0]-cx, dy = vb[j*3+1]-cy, dz = vb[j*3+2]-cz;
        float n = sqrtf(dx*dx+dy*dy+dz*dz);
        float inv = 1.0f / fmaxf(n, 1e-12f);
        sdx[t]=dx*inv; sdy[t]=dy*inv; sdz[t]=dz*inv;
    }
    __syncthreads();
    int k = t;
    float d0 = dir0[k], d1 = dir0[128+k], d2 = dir0[256+k];
    float n = sqrtf(d0*d0+d1*d1+d2*d2);
    float inv = 1.0f / fmaxf(n, 1e-12f);
    d0*=inv; d1*=inv; d2*=inv;
    float m = 0.0f;
#pragma unroll
    for (int j=0;j<KNN;j++)
        m = fmaxf(m, sdx[j]*d0 + sdy[j]*d1 + sdz[j]*d2);
    fm0[(size_t)bv*128 + k] = m;
}

// ---------------- conv_layer epilogue ----------------------------------------
template<int COUT, bool RELU>
__global__ void conv_layer_kernel(const float* __restrict__ verts, int V,
                                  const int* __restrict__ nb,
                                  const float* __restrict__ f,
                                  const float* __restrict__ dirs,
                                  float* __restrict__ out)
{
    int bv = blockIdx.x;
    int b = bv / V, v = bv - b*V;
    const float* vb = verts + (size_t)b*V*3;
    __shared__ float sdx[KNN], sdy[KNN], sdz[KNN];
    __shared__ int   si[KNN];
    int t = threadIdx.x;
    float cx = vb[v*3+0], cy = vb[v*3+1], cz = vb[v*3+2];
    if (t < KNN) {
        int j = nb[(size_t)bv*KNN + t];
        si[t] = j;
        float dx = vb[j*3+0]-cx, dy = vb[j*3+1]-cy, dz = vb[j*3+2]-cz;
        float n = sqrtf(dx*dx+dy*dy+dz*dz);
        float inv = 1.0f / fmaxf(n, 1e-12f);
        sdx[t]=dx*inv; sdy[t]=dy*inv; sdz[t]=dz*inv;
    }
    __syncthreads();
    const float* fb = f + (size_t)b*V*(2*COUT);
    for (int co = t; co < COUT; co += blockDim.x) {
        float d0 = dirs[co], d1 = dirs[COUT+co], d2 = dirs[2*COUT+co];
        float n = sqrtf(d0*d0+d1*d1+d2*d2);
        float inv = 1.0f / fmaxf(n, 1e-12f);
        d0*=inv; d1*=inv; d2*=inv;
        float m = -3.4e38f;
#pragma unroll 8
        for (int j=0;j<KNN;j++) {
            float th = fmaxf(sdx[j]*d0 + sdy[j]*d1 + sdz[j]*d2, 0.0f);
            float val = th * fb[(size_t)si[j]*(2*COUT) + COUT + co];
            m = fmaxf(m, val);
        }
        float r = fb[(size_t)v*(2*COUT) + co] + m;
        out[((size_t)b*V+v)*COUT + co] = RELU ? fmaxf(r, 0.0f) : r;
    }
}

// ---------------- pool ------------------------------------------------------
__global__ void pool_kernel(const float* __restrict__ verts,
                            const float* __restrict__ fm,
                            int V, int C,
                            const int* __restrict__ sidx,
                            const int* __restrict__ nb4, int ns,
                            float* __restrict__ vout, float* __restrict__ fout)
{
    int bq = blockIdx.x;
    int b = bq / ns, q = bq - b*ns;
    int t = threadIdx.x;
    int sv = sidx[q];
    if (t < 3) vout[(size_t)bq*3 + t] = verts[((size_t)b*V + sv)*3 + t];
    const int* nbq = nb4 + (size_t)bq*4;
    int j0=nbq[0], j1=nbq[1], j2=nbq[2], j3=nbq[3];
    const float* fb = fm + (size_t)b*V*C;
    for (int c=t; c<C; c+=blockDim.x) {
        float m = fmaxf(fmaxf(fb[(size_t)j0*C+c], fb[(size_t)j1*C+c]),
                        fmaxf(fb[(size_t)j2*C+c], fb[(size_t)j3*C+c]));
        fout[(size_t)bq*C + c] = m;
    }
}

// ---------------- nearest ---------------------------------------------------
__global__ void nearest_kernel(const float* __restrict__ verts,
                               const float* __restrict__ src,
                               int V, int S, int* __restrict__ out)
{
    int b = blockIdx.y;
    int q = blockIdx.x * 128 + threadIdx.x;
    const float* vb = verts + (size_t)b*V*3;
    const float* sb = src + (size_t)b*S*3;
    float qx = vb[q*3+0], qy = vb[q*3+1], qz = vb[q*3+2];
    float qa2 = qx*qx + qy*qy + qz*qz;
    float best = 3.4e38f; int bi = 0;
    __shared__ float4 sp[128];
    for (int t0=0; t0<S; t0+=128) {
        int j = t0 + threadIdx.x;
        float x = sb[j*3+0], y = sb[j*3+1], z = sb[j*3+2];
        sp[threadIdx.x] = make_float4(x,y,z, x*x+y*y+z*z);
        __syncthreads();
        for (int jj=0; jj<128; jj++) {
            float4 p = sp[jj];
            float d = qa2 + p.w - 2.0f*(qx*p.x + qy*p.y + qz*p.z);
            if (d < best) { best = d; bi = t0+jj; }
        }
        __syncthreads();
    }
    out[(size_t)b*V + q] = bi;
}

// ---------------- global feature --------------------------------------------
__global__ void fglobal_kernel(const float* __restrict__ fm4, float* __restrict__ g)
{
    int b = blockIdx.x, c = threadIdx.x;
    float m = -3.4e38f;
    for (int v=0; v<NP2; v++) m = fmaxf(m, fm4[((size_t)b*NP2+v)*512 + c]);
    g[(size_t)b*512 + c] = m;
}

// ---------------- fuse assembly -> bf16 hi/lo ---------------------------------
__global__ void fuse_kernel(const float* __restrict__ fm0, const float* __restrict__ fm1,
                            const float* __restrict__ fm2, const float* __restrict__ fm3,
                            const float* __restrict__ fm4, const float* __restrict__ fg,
                            const int* __restrict__ near1, const int* __restrict__ near2,
                            bf16* __restrict__ fhi, bf16* __restrict__ flo)
{
    int bv = blockIdx.x;
    int b = bv >> 12;
    int n1 = near1[bv], n2 = near2[bv];
    size_t o = (size_t)bv*1792;
    for (int c = threadIdx.x; c < 1792; c += blockDim.x) {
        float val;
        if (c < 128)        val = fm0[(size_t)bv*128 + c];
        else if (c < 256)   val = fm1[(size_t)bv*128 + (c-128)];
        else if (c < 512)   val = fm2[((size_t)b*NP1+n1)*256 + (c-256)];
        else if (c < 768)   val = fm3[((size_t)b*NP1+n1)*256 + (c-512)];
        else if (c < 1280)  val = fm4[((size_t)b*NP2+n2)*512 + (c-768)];
        else                val = fg [(size_t)b*512 + (c-1280)];
        bf16 h = __float2bfloat16(val);
        fhi[o+c] = h;
        flo[o+c] = __float2bfloat16(val - __bfloat162float(h));
    }
}

// ---------------- scalar SGEMM (for small f-layer GEMMs) ---------------------
#define SMS 132
template<bool BT, bool RELU>
__global__ __launch_bounds__(256, 2)
void gemm128(const float* __restrict__ A, const float* __restrict__ B,
             const float* __restrict__ bias, float* __restrict__ C,
             int M, int N, int K)
{
    __shared__ __align__(16) float As[2][8*SMS];
    __shared__ __align__(16) float Bs[2][8*SMS];
    const int tid = threadIdx.x;
    const int tx = tid & 15;
    const int ty = tid >> 4;
    const int m0 = blockIdx.y * 128;
    const int n0 = blockIdx.x * 128;

    const int arow = tid >> 1;
    const int akp  = (tid & 1) * 4;
    const float* Aptr = A + (size_t)(m0 + arow) * K + akp;

    const float* Bptr;
    int bkk = 0, bn4 = 0;
    if (BT) {
        Bptr = B + (size_t)(n0 + arow) * K + akp;
    } else {
        bkk = tid >> 5; bn4 = (tid & 31) * 4;
        Bptr = B + (size_t)bkk * N + n0 + bn4;
    }

    float acc[8][8];
#pragma unroll
    for (int i=0;i<8;i++)
#pragma unroll
        for (int j=0;j<8;j++) acc[i][j]=0.f;

    const int NT = K >> 3;

    float4 areg = *(const float4*)Aptr;
    float4 breg = *(const float4*)Bptr;
    As[0][(akp+0)*SMS+arow]=areg.x;
    As[0][(akp+1)*SMS+arow]=areg.y;
    As[0][(akp+2)*SMS+arow]=areg.z;
    As[0][(akp+3)*SMS+arow]=areg.w;
    if (BT) {
        Bs[0][(akp+0)*SMS+arow]=breg.x;
        Bs[0][(akp+1)*SMS+arow]=breg.y;
        Bs[0][(akp+2)*SMS+arow]=breg.z;
        Bs[0][(akp+3)*SMS+arow]=breg.w;
    } else {
        *(float4*)&Bs[0][bkk*SMS+bn4] = breg;
    }
    __syncthreads();

    for (int kt=0; kt<NT; kt++) {
        const int cur = kt & 1;
        if (kt+1 < NT) {
            areg = *(const float4*)(Aptr + (size_t)(kt+1)*8);
            if (BT) breg = *(const float4*)(Bptr + (size_t)(kt+1)*8);
            else    breg = *(const float4*)(Bptr + (size_t)(kt+1)*8*N);
        }
        const float* as = As[cur];
        const float* bs = Bs[cur];
#pragma unroll
        for (int kk=0; kk<8; kk++) {
            float4 a0 = *(const float4*)&as[kk*SMS + ty*4];
            float4 a1 = *(const float4*)&as[kk*SMS + 64 + ty*4];
            float4 b0 = *(const float4*)&bs[kk*SMS + tx*4];
            float4 b1 = *(const float4*)&bs[kk*SMS + 64 + tx*4];
            float av[8] = {a0.x,a0.y,a0.z,a0.w,a1.x,a1.y,a1.z,a1.w};
            float bv[8] = {b0.x,b0.y,b0.z,b0.w,b1.x,b1.y,b1.z,b1.w};
#pragma unroll
            for (int i=0;i<8;i++)
#pragma unroll
                for (int j=0;j<8;j++)
                    acc[i][j] += av[i]*bv[j];
        }
        if (kt+1 < NT) {
            const int nxt = cur ^ 1;
            As[nxt][(akp+0)*SMS+arow]=areg.x;
            As[nxt][(akp+1)*SMS+arow]=areg.y;
            As[nxt][(akp+2)*SMS+arow]=areg.z;
            As[nxt][(akp+3)*SMS+arow]=areg.w;
            if (BT) {
                Bs[nxt][(akp+0)*SMS+arow]=breg.x;
                Bs[nxt][(akp+1)*SMS+arow]=breg.y;
                Bs[nxt][(akp+2)*SMS+arow]=breg.z;
                Bs[nxt][(akp+3)*SMS+arow]=breg.w;
            } else {
                *(float4*)&Bs[nxt][bkk*SMS+bn4] = breg;
            }
        }
        __syncthreads();
    }

#pragma unroll
    for (int ih=0; ih<2; ih++)
#pragma unroll
    for (int ii=0; ii<4; ii++) {
        const int i = ih*4 + ii;
        const int gm = m0 + ih*64 + ty*4 + ii;
        if (gm >= M) continue;
        float* crow = C + (size_t)gm*N + n0;
#pragma unroll
        for (int jh=0; jh<2; jh++) {
            const int cb = jh*64 + tx*4;
            if (n0 + cb >= N) continue;
            float4 bv = *(const float4*)&bias[n0 + cb];
            float4 v;
            v.x = acc[i][jh*4+0] + bv.x;
            v.y = acc[i][jh*4+1] + bv.y;
            v.z = acc[i][jh*4+2] + bv.z;
            v.w = acc[i][jh*4+3] + bv.w;
            if (RELU) {
                v.x = fmaxf(v.x, 0.f); v.y = fmaxf(v.y, 0.f);
                v.z = fmaxf(v.z, 0.f); v.w = fmaxf(v.w, 0.f);
            }
            *(float4*)&crow[cb] = v;
        }
    }
}

// ---------------- head: out(16 rows x 13) = h2 @ cw3^T + cb3 ----------------
__global__ void head_kernel(const float* __restrict__ h2,
                            const float* __restrict__ cw3,
                            const float* __restrict__ cb3,
                            float* __restrict__ out)
{
    __shared__ float sh[16][512];
    __shared__ float sw[13*513];
    const int tid = threadIdx.x;
    const int r = tid >> 4, c = tid & 15;
    const int row0 = blockIdx.x * 16;
    for (int i = tid; i < 16*512; i += 256)
        sh[i>>9][i&511] = h2[(size_t)row0*512 + i];
    for (int i = tid; i < 13*512; i += 256)
        sw[(i>>9)*513 + (i&511)] = cw3[i];
    __syncthreads();
    if (c < 13) {
        float acc = cb3[c];
        const float* w = &sw[c*513];
        const float* hrow = sh[r];
#pragma unroll 8
        for (int k=0;k<512;k++) acc += hrow[k]*w[k];
        out[(size_t)(row0+r)*13 + c] = acc;
    }
}

// -----------------------------------------------------------------------------
static void* sym_addr(const void* symbol) {
    void* p = nullptr;
    cudaGetSymbolAddress(&p, symbol);
    return p;
}

extern "C" void kernel_launch(void* const* d_in, const int* in_sizes, int n_in,
                              void* d_out, int out_size)
{
    (void)in_sizes; (void)n_in; (void)out_size;
    const float* vertices = (const float*)d_in[0];
    const int*   sidx1    = (const int*)  d_in[1];
    const int*   sidx2    = (const int*)  d_in[2];
    const float* dir0     = (const float*)d_in[3];
    const float* w1 = (const float*)d_in[4];  const float* b1 = (const float*)d_in[5];  const float* d1 = (const float*)d_in[6];
    const float* w2 = (const float*)d_in[7];  const float* b2 = (const float*)d_in[8];  const float* d2 = (const float*)d_in[9];
    const float* w3 = (const float*)d_in[10]; const float* b3 = (const float*)d_in[11]; const float* d3 = (const float*)d_in[12];
    const float* w4 = (const float*)d_in[13]; const float* b4 = (const float*)d_in[14]; const float* d4 = (const float*)d_in[15];
    const float* cw1 = (const float*)d_in[16]; const float* cb1 = (const float*)d_in[17];
    const float* cw2 = (const float*)d_in[18]; const float* cb2 = (const float*)d_in[19];
    const float* cw3 = (const float*)d_in[20]; const float* cb3 = (const float*)d_in[21];
    float* out = (float*)d_out;

    int*   nb1   = (int*)  sym_addr(g_nb1);
    int*   nb2   = (int*)  sym_addr(g_nb2);
    int*   nb3   = (int*)  sym_addr(g_nb3);
    int*   nbp   = (int*)  sym_addr(g_nbp);
    int*   near1 = (int*)  sym_addr(g_near1);
    int*   near2 = (int*)  sym_addr(g_near2);
    float* fm0   = (float*)sym_addr(g_fm0);
    float* fm1   = (float*)sym_addr(g_fm1);
    float* fbuf  = (float*)sym_addr(g_f);
    float* vp1   = (float*)sym_addr(g_vp1);
    float* fmp1  = (float*)sym_addr(g_fmp1);
    float* fm2   = (float*)sym_addr(g_fm2);
    float* fm3   = (float*)sym_addr(g_fm3);
    float* vp2   = (float*)sym_addr(g_vp2);
    float* fmp2  = (float*)sym_addr(g_fmp2);
    float* fm4   = (float*)sym_addr(g_fm4);
    float* fglob = (float*)sym_addr(g_fglob);
    float* h2    = (float*)sym_addr(g_h2);
    bf16* fusehi = (bf16*)sym_addr(g_fusehi);
    bf16* fuselo = (bf16*)sym_addr(g_fuselo);
    bf16* h1hi   = (bf16*)sym_addr(g_h1hi);
    bf16* h1lo   = (bf16*)sym_addr(g_h1lo);
    bf16* cw1hi  = (bf16*)sym_addr(g_cw1hi);
    bf16* cw1lo  = (bf16*)sym_addr(g_cw1lo);
    bf16* cw2hi  = (bf16*)sym_addr(g_cw2hi);
    bf16* cw2lo  = (bf16*)sym_addr(g_cw2lo);

    cudaFuncSetAttribute(mma_gemm<1792,true,true>,  cudaFuncAttributeMaxDynamicSharedMemorySize, MMA_SMEM_TOTAL);
    cudaFuncSetAttribute(mma_gemm<512,true,false>,  cudaFuncAttributeMaxDynamicSharedMemorySize, MMA_SMEM_TOTAL);

    // weight splits (independent, run first)
    split_kernel<<<(512*1792+255)/256, 256>>>(cw1, cw1hi, cw1lo, 512*1792);
    split_kernel<<<(512*512+255)/256, 256>>>(cw2, cw2hi, cw2lo, 512*512);

    // 1. full-res KNN(32)
    knn_kernel<KNN><<<dim3(NV/128, BSZ), 128>>>(vertices, nullptr, NV, NV, nb1);
    // 2. fm0 = conv_surface
    conv_surface_kernel<<<BSZ*NV, 128>>>(vertices, nb1, dir0, fm0);
    // 3-4. fm1
    gemm128<false,false><<<dim3(2, (BSZ*NV)/128), 256>>>(fm0, w1, b1, fbuf, BSZ*NV, 256, 128);
    conv_layer_kernel<128,true><<<BSZ*NV, 128>>>(vertices, NV, nb1, fbuf, d1, fm1);
    // 5-6. pool1
    knn_kernel<4><<<dim3(NP1/128, BSZ), 128>>>(vertices, sidx1, NP1, NV, nbp);
    pool_kernel<<<BSZ*NP1, 128>>>(vertices, fm1, NV, 128, sidx1, nbp, NP1, vp1, fmp1);
    // 7. KNN level 1
    knn_kernel<KNN><<<dim3(NP1/128, BSZ), 128>>>(vp1, nullptr, NP1, NP1, nb2);
    // 8-9. fm2
    gemm128<false,false><<<dim3(4, (BSZ*NP1)/128), 256>>>(fmp1, w2, b2, fbuf, BSZ*NP1, 512, 128);
    conv_layer_kernel<256,true><<<BSZ*NP1, 256>>>(vp1, NP1, nb2, fbuf, d2, fm2);
    // 10-11. fm3
    gemm128<false,false><<<dim3(4, (BSZ*NP1)/128), 256>>>(fm2, w3, b3, fbuf, BSZ*NP1, 512, 256);
    conv_layer_kernel<256,true><<<BSZ*NP1, 256>>>(vp1, NP1, nb2, fbuf, d3, fm3);
    // 12-13. pool2
    knn_kernel<4><<<dim3(NP2/128, BSZ), 128>>>(vp1, sidx2, NP2, NP1, nbp);
    pool_kernel<<<BSZ*NP2, 256>>>(vp1, fm3, NP1, 256, sidx2, nbp, NP2, vp2, fmp2);
    // 14. KNN level 2
    knn_kernel<KNN><<<dim3(NP2/128, BSZ), 128>>>(vp2, nullptr, NP2, NP2, nb3);
    // 15-16. fm4
    gemm128<false,false><<<dim3(8, (BSZ*NP2)/128), 256>>>(fmp2, w4, b4, fbuf, BSZ*NP2, 1024, 256);
    conv_layer_kernel<512,false><<<BSZ*NP2, 256>>>(vp2, NP2, nb3, fbuf, d4, fm4);
    // 17. global max feature
    fglobal_kernel<<<BSZ, 512>>>(fm4, fglob);
    // 18. nearest upsample indices
    nearest_kernel<<<dim3(NV/128, BSZ), 128>>>(vertices, vp1, NV, NP1, near1);
    nearest_kernel<<<dim3(NV/128, BSZ), 128>>>(vertices, vp2, NV, NP2, near2);
    // 19. fuse -> bf16 hi/lo directly
    fuse_kernel<<<BSZ*NV, 256>>>(fm0, fm1, fm2, fm3, fm4, fglob, near1, near2, fusehi, fuselo);
    // 20. h1 = relu(fuse @ cw1^T + cb1)  [warp-MMA split bf16, emits bf16 hi/lo]
    mma_gemm<1792,true,true><<<dim3(4, (BSZ*NV)/128), 256, MMA_SMEM_TOTAL>>>(
        fusehi, fuselo, cw1hi, cw1lo, cb1, 512, nullptr, h1hi, h1lo);
    // 21. h2 = relu(h1 @ cw2^T + cb2)  [warp-MMA, emits fp32]
    mma_gemm<512,true,false><<<dim3(4, (BSZ*NV)/128), 256, MMA_SMEM_TOTAL>>>(
        h1hi, h1lo, cw2hi, cw2lo, cb2, 512, h2, nullptr, nullptr);
    // 22. logits
    head_kernel<<<(BSZ*NV)/16, 256>>>(h2, cw3, cb3, out);
}